// round 7
// baseline (speedup 1.0000x reference)
#include <cuda_runtime.h>
#include <cstddef>
#include <cstdint>

// MoEGate fused single-kernel: logits = x @ W^T, softmax, top-6 (+renorm),
// seq-aux loss. x: [T=16384, h=2048] f32, W: [E=64, h] f32.
// Output layout (f32): [topk_idx (T*6) | topk_weight (T*6) | aux_loss (1)]
//
// GEMM engine: fma.rn.f32x2, halves = even/odd-k partial sums (operands
// naturally contiguous in smem). 8 tokens/warp x 2 experts/lane.
// cp.async double-buffered 64-wide k-chunks.
// Aux loss: per-block partials -> __device__ scratch (fully overwritten,
// no zeroing needed), self-resetting ticket, last block reduces. Single
// launch per run (graph-capturable, deterministic).

#define NE 64
#define KTOP 6
#define NB 4
#define TPB 32               // tokens per block
#define THREADS 128          // 4 warps, 8 tokens/warp
#define CHUNK 64             // k elements per stage
#define PITCH 68             // floats per staged row (odd quad stride 17 -> conflict-free)
#define NBLK 512             // T / TPB
#define BPB 128              // blocks per batch = NBLK / NB

__device__ float g_pscore[NBLK * NE];
__device__ int   g_pcnt[NBLK * NE];
__device__ unsigned g_ticket;   // zero-init; last block resets -> replay-safe

static __device__ __forceinline__ void ffma2(unsigned long long& d,
                                             unsigned long long a,
                                             unsigned long long b) {
    asm("fma.rn.f32x2 %0, %1, %2, %0;" : "+l"(d) : "l"(a), "l"(b));
}
static __device__ __forceinline__ void add2(unsigned long long& d,
                                            unsigned long long a) {
    asm("add.rn.f32x2 %0, %0, %1;" : "+l"(d) : "l"(a));
}
static __device__ __forceinline__ void cpa16(uint32_t dst, const void* src) {
    asm volatile("cp.async.cg.shared.global [%0], [%1], 16;"
                 :: "r"(dst), "l"(src));
}

__global__ __launch_bounds__(THREADS, 4) void moe_gate_kernel(
    const float* __restrict__ x, const float* __restrict__ w,
    float* __restrict__ out, int h, int T, int S)
{
    __shared__ __align__(16) float xs[2][TPB * PITCH];
    __shared__ __align__(16) float ws[2][NE * PITCH];
    __shared__ float score_acc[NE];
    __shared__ int   cnt_acc[NE];
    __shared__ unsigned is_last;

    const int tid  = threadIdx.x;
    const int lane = tid & 31;
    const int warp = tid >> 5;
    const int bid  = blockIdx.x;
    const int tok0 = bid * TPB;
    const int nchunk = h / CHUNK;

    if (tid < NE) { score_acc[tid] = 0.0f; cnt_acc[tid] = 0; }

    unsigned long long acc[8][2], sum[8][2];
#pragma unroll
    for (int t = 0; t < 8; t++) {
        acc[t][0] = 0ull; acc[t][1] = 0ull;
        sum[t][0] = 0ull; sum[t][1] = 0ull;
    }

    // staging: 96 rows (32 x + 64 w) x 16 quads = 1536 jobs / 128 thr = 12
    auto stage = [&](int k0, int buf) {
#pragma unroll
        for (int j = 0; j < 12; j++) {
            int c = tid + j * THREADS;
            int row = c >> 4, q = c & 15;
            const float* src;
            float* dst;
            if (row < TPB) {
                src = x + (size_t)(tok0 + row) * h + k0 + q * 4;
                dst = &xs[buf][row * PITCH + q * 4];
            } else {
                int e = row - TPB;
                src = w + (size_t)e * h + k0 + q * 4;
                dst = &ws[buf][e * PITCH + q * 4];
            }
            cpa16((uint32_t)__cvta_generic_to_shared(dst), src);
        }
    };

    stage(0, 0);
    asm volatile("cp.async.commit_group;" ::: "memory");

    for (int c = 0; c < nchunk; c++) {
        const int buf = c & 1;
        asm volatile("cp.async.wait_group 0;" ::: "memory");
        __syncthreads();

        if (c + 1 < nchunk) {
            stage((c + 1) * CHUNK, buf ^ 1);
            asm volatile("cp.async.commit_group;" ::: "memory");
        }

        const float* xb = &xs[buf][(warp * 8) * PITCH];
        const float* wb = &ws[buf][0];
#pragma unroll
        for (int kk = 0; kk < CHUNK; kk += 4) {
            ulonglong2 w0 = *(const ulonglong2*)(wb + lane * PITCH + kk);
            ulonglong2 w1 = *(const ulonglong2*)(wb + (lane + 32) * PITCH + kk);
#pragma unroll
            for (int t = 0; t < 8; t++) {
                ulonglong2 xv = *(const ulonglong2*)(xb + t * PITCH + kk);
                ffma2(acc[t][0], xv.x, w0.x);
                ffma2(acc[t][0], xv.y, w0.y);
                ffma2(acc[t][1], xv.x, w1.x);
                ffma2(acc[t][1], xv.y, w1.y);
            }
        }
#pragma unroll
        for (int t = 0; t < 8; t++) {
            add2(sum[t][0], acc[t][0]); acc[t][0] = 0ull;
            add2(sum[t][1], acc[t][1]); acc[t][1] = 0ull;
        }
    }

    // ---- epilogue: warp owns 8 tokens; lane owns experts lane, lane+32
    union Cv { unsigned long long u; float2 f; };
    for (int j = 0; j < 8; j++) {
        const int t  = warp * 8 + j;
        const int gt = tok0 + t;
        Cv c0, c1; c0.u = sum[j][0]; c1.u = sum[j][1];
        float v0 = c0.f.x + c0.f.y;
        float v1 = c1.f.x + c1.f.y;

        float m = fmaxf(v0, v1);
#pragma unroll
        for (int off = 16; off; off >>= 1)
            m = fmaxf(m, __shfl_xor_sync(0xffffffffu, m, off));

        float e0 = __expf(v0 - m), e1 = __expf(v1 - m);
        float z = e0 + e1;
#pragma unroll
        for (int off = 16; off; off >>= 1)
            z += __shfl_xor_sync(0xffffffffu, z, off);
        float inv = 1.0f / z;
        float s0 = e0 * inv, s1 = e1 * inv;

        atomicAdd(&score_acc[lane],      s0);
        atomicAdd(&score_acc[lane + 32], s1);

        // top-6 on LOGITS (order-identical to softmax), lowest-index ties
        float a0 = v0, a1 = v1;
        float myw = 0.0f; int myi = 0;
        float wsum = 0.0f;
#pragma unroll
        for (int it = 0; it < KTOP; it++) {
            float bv; int bi;
            if (a0 >= a1) { bv = a0; bi = lane; }
            else          { bv = a1; bi = lane + 32; }
#pragma unroll
            for (int off = 16; off; off >>= 1) {
                float ov = __shfl_xor_sync(0xffffffffu, bv, off);
                int   oi = __shfl_xor_sync(0xffffffffu, bi, off);
                if (ov > bv || (ov == bv && oi < bi)) { bv = ov; bi = oi; }
            }
            float cand = (bi < 32) ? s0 : s1;
            float sc = __shfl_sync(0xffffffffu, cand, bi & 31);
            wsum += sc;
            if (lane == it) { myw = sc; myi = bi; }
            if (bi == lane)      a0 = -3.4e38f;
            if (bi == lane + 32) a1 = -3.4e38f;
            if (lane == 0) atomicAdd(&cnt_acc[bi], 1);
        }
        if (lane < KTOP) {
            out[(size_t)gt * KTOP + lane] = (float)myi;
            out[(size_t)T * KTOP + (size_t)gt * KTOP + lane] =
                myw / (wsum + 1e-20f);
        }
    }
    __syncthreads();

    // ---- per-block partials + last-block aux reduction (no pre-zeroing)
    if (tid < NE) {
        g_pscore[bid * NE + tid] = score_acc[tid];
        g_pcnt[bid * NE + tid]   = cnt_acc[tid];
    }
    __threadfence();
    __syncthreads();
    if (tid == 0) {
        unsigned tkt = atomicAdd(&g_ticket, 1u);
        is_last = (tkt == (unsigned)(gridDim.x - 1));
    }
    __syncthreads();

    if (is_last) {
        if (tid == 0) g_ticket = 0;   // reset for next graph replay
        __threadfence();
        float local = 0.0f;
        for (int p = tid; p < NB * NE; p += THREADS) {
            int b = p >> 6, e = p & 63;
            float sc = 0.0f; int cn = 0;
            const int base = b * BPB;
            for (int blk = 0; blk < BPB; blk++) {
                sc += g_pscore[(base + blk) * NE + e];
                cn += g_pcnt[(base + blk) * NE + e];
            }
            float ce = (float)cn * ((float)NE / ((float)S * (float)KTOP));
            local += ce * (sc / (float)S);
        }
#pragma unroll
        for (int off = 16; off; off >>= 1)
            local += __shfl_xor_sync(0xffffffffu, local, off);
        __shared__ float part[4];
        if (lane == 0) part[warp] = local;
        __syncthreads();
        if (tid == 0) {
            float s = part[0] + part[1] + part[2] + part[3];
            out[(size_t)2 * T * KTOP] = (s / (float)NB) * 1e-3f;
        }
    }
}

extern "C" void kernel_launch(void* const* d_in, const int* in_sizes, int n_in,
                              void* d_out, int out_size) {
    const float* x = (const float*)d_in[0];
    const float* w = (const float*)d_in[1];
    float* out = (float*)d_out;
    int h = in_sizes[1] / NE;     // 2048
    int T = in_sizes[0] / h;      // 16384
    int S = T / NB;               // 4096

    moe_gate_kernel<<<T / TPB, THREADS>>>(x, w, out, h, T, S);
}